// round 3
// baseline (speedup 1.0000x reference)
#include <cuda_runtime.h>
#include <cuda_bf16.h>
#include <cstddef>

// Problem constants
#define B_    8
#define N_    1024
#define DIM_  768
#define HEADS 12
#define DH    64
#define INNER 768          // HEADS*DH
#define QKV3  2304         // 3*INNER
#define SCALE 0.125f       // DH^-0.5

// Scratch (device globals: allocation-free rule)
__device__ float g_qkv[(size_t)B_ * N_ * QKV3];   // [b, n, 3*inner]
__device__ float g_att[(size_t)B_ * N_ * INNER];  // [b, n, h*DH+d]

// ---------------------------------------------------------------------------
// Tiled FP32 GEMM: C[M,N] = A[M,K] * B[K,N]
// BM=128, BN=64, BK=16, 256 threads, 8x4 micro-tile per thread.
// ---------------------------------------------------------------------------
#define BM 128
#define BN 64
#define BK 16
#define AS_STRIDE (BM + 4)   // 132 floats, 528B rows (16B multiple)
#define BS_STRIDE (BN + 4)   // 68  floats, 272B rows (16B multiple)

__global__ __launch_bounds__(256) void gemm_kernel(
    const float* __restrict__ A, const float* __restrict__ Bm,
    float* __restrict__ C, int M, int N, int K)
{
    __shared__ float As[BK][AS_STRIDE];   // transposed: As[k][m]
    __shared__ float Bs[BK][BS_STRIDE];   // Bs[k][n]

    const int tid = threadIdx.x;
    const int tx  = tid & 15;     // 0..15 -> N micro
    const int ty  = tid >> 4;     // 0..15 -> M micro
    const int row0 = blockIdx.y * BM;
    const int col0 = blockIdx.x * BN;

    float acc[8][4];
    #pragma unroll
    for (int i = 0; i < 8; i++)
        #pragma unroll
        for (int j = 0; j < 4; j++) acc[i][j] = 0.f;

    for (int k0 = 0; k0 < K; k0 += BK) {
        // A tile: 128x16 = 2048 elems, 8 per thread
        #pragma unroll
        for (int i = 0; i < 8; i++) {
            int idx = tid + i * 256;
            int r = idx >> 4, c = idx & 15;
            As[c][r] = A[(size_t)(row0 + r) * K + (k0 + c)];
        }
        // B tile: 16x64 = 1024 elems, 4 per thread
        #pragma unroll
        for (int i = 0; i < 4; i++) {
            int idx = tid + i * 256;
            int r = idx >> 6, c = idx & 63;
            Bs[r][c] = Bm[(size_t)(k0 + r) * N + (col0 + c)];
        }
        __syncthreads();

        #pragma unroll
        for (int kk = 0; kk < BK; kk++) {
            float4 a0 = *(const float4*)&As[kk][ty * 8];
            float4 a1 = *(const float4*)&As[kk][ty * 8 + 4];
            float4 b0 = *(const float4*)&Bs[kk][tx * 4];
            float a[8] = {a0.x, a0.y, a0.z, a0.w, a1.x, a1.y, a1.z, a1.w};
            float b[4] = {b0.x, b0.y, b0.z, b0.w};
            #pragma unroll
            for (int i = 0; i < 8; i++)
                #pragma unroll
                for (int j = 0; j < 4; j++)
                    acc[i][j] = fmaf(a[i], b[j], acc[i][j]);
        }
        __syncthreads();
    }

    #pragma unroll
    for (int i = 0; i < 8; i++) {
        size_t rbase = (size_t)(row0 + ty * 8 + i) * N + col0 + tx * 4;
        #pragma unroll
        for (int j = 0; j < 4; j++)
            C[rbase + j] = acc[i][j];
    }
}

// ---------------------------------------------------------------------------
// Fused shuffled-Q flash attention.
// Grid: (B*HEADS, N/64). Block: 256 threads (16x16), 64 query rows per block.
// Q gathered through perm at load. Online softmax, 64-wide K/V tiles.
// ---------------------------------------------------------------------------
#define RS 68   // smem row stride (floats); 272B rows, 16B aligned
#define ATTN_SMEM (4 * 64 * RS * sizeof(float))   // Qs,Ks,Vt,Ps = 69632 B

__global__ __launch_bounds__(256) void attn_kernel(
    const float* __restrict__ qkv, const int* __restrict__ perm,
    float* __restrict__ out)
{
    extern __shared__ float sm[];
    float* Qs = sm;                  // [64][RS]  Qs[r][d]
    float* Ks = sm + 64 * RS;        // [64][RS]  Ks[c][d]
    float* Vt = sm + 2 * 64 * RS;    // [64][RS]  Vt[d][j]  (transposed)
    float* Ps = sm + 3 * 64 * RS;    // [64][RS]  Ps[r][j]

    const int bh = blockIdx.x;
    const int b  = bh / HEADS, h = bh % HEADS;
    const int rt = blockIdx.y;           // query row tile
    const int tid = threadIdx.x;
    const int tx = tid & 15, ty = tid >> 4;

    const float* base = qkv + (size_t)b * N_ * QKV3;

    // Load shuffled Q tile: row r element d = qflat[perm[(rt*64+r)*64 + d]]
    #pragma unroll
    for (int i = 0; i < 16; i++) {
        int idx = tid + i * 256;           // 0..4095
        int r = idx >> 6, d = idx & 63;
        int p  = perm[((rt * 64 + r) << 6) + d];
        int n2 = p >> 6, d2 = p & 63;
        Qs[r * RS + d] = base[(size_t)n2 * QKV3 + h * DH + d2];
    }

    float m[4], l[4], acc[4][4];
    #pragma unroll
    for (int i = 0; i < 4; i++) {
        m[i] = -1e30f; l[i] = 0.f;
        #pragma unroll
        for (int j = 0; j < 4; j++) acc[i][j] = 0.f;
    }

    for (int j0 = 0; j0 < N_; j0 += 64) {
        __syncthreads();   // prior P@V done before K/V/P reuse
        // Load K rows + V transposed
        #pragma unroll
        for (int i = 0; i < 16; i++) {
            int idx = tid + i * 256;
            int r = idx >> 6, d = idx & 63;
            const float* rowp = base + (size_t)(j0 + r) * QKV3;
            Ks[r * RS + d] = rowp[INNER + h * DH + d];
            Vt[d * RS + r] = rowp[2 * INNER + h * DH + d];
        }
        __syncthreads();

        // S = Q K^T (4x4 per thread), float4 over d
        float s[4][4];
        #pragma unroll
        for (int i = 0; i < 4; i++)
            #pragma unroll
            for (int j = 0; j < 4; j++) s[i][j] = 0.f;

        #pragma unroll
        for (int dq = 0; dq < 16; dq++) {
            float4 a4[4], b4[4];
            #pragma unroll
            for (int i = 0; i < 4; i++)
                a4[i] = *(const float4*)&Qs[(ty * 4 + i) * RS + dq * 4];
            #pragma unroll
            for (int j = 0; j < 4; j++)
                b4[j] = *(const float4*)&Ks[(tx * 4 + j) * RS + dq * 4];
            #pragma unroll
            for (int i = 0; i < 4; i++)
                #pragma unroll
                for (int j = 0; j < 4; j++) {
                    s[i][j] = fmaf(a4[i].x, b4[j].x, s[i][j]);
                    s[i][j] = fmaf(a4[i].y, b4[j].y, s[i][j]);
                    s[i][j] = fmaf(a4[i].z, b4[j].z, s[i][j]);
                    s[i][j] = fmaf(a4[i].w, b4[j].w, s[i][j]);
                }
        }

        // Online softmax per row (rows owned by ty-group; reduce over 16 tx lanes)
        #pragma unroll
        for (int i = 0; i < 4; i++) {
            float mx = -1e30f;
            #pragma unroll
            for (int j = 0; j < 4; j++) {
                s[i][j] *= SCALE;
                mx = fmaxf(mx, s[i][j]);
            }
            #pragma unroll
            for (int off = 8; off; off >>= 1)
                mx = fmaxf(mx, __shfl_xor_sync(0xffffffffu, mx, off, 16));
            float mnew  = fmaxf(m[i], mx);
            float alpha = __expf(m[i] - mnew);
            float rs = 0.f;
            #pragma unroll
            for (int j = 0; j < 4; j++) {
                float e = __expf(s[i][j] - mnew);
                s[i][j] = e;
                rs += e;
            }
            #pragma unroll
            for (int off = 8; off; off >>= 1)
                rs += __shfl_xor_sync(0xffffffffu, rs, off, 16);
            l[i] = l[i] * alpha + rs;
            m[i] = mnew;
            #pragma unroll
            for (int j = 0; j < 4; j++) acc[i][j] *= alpha;
            *(float4*)&Ps[(ty * 4 + i) * RS + tx * 4] =
                make_float4(s[i][0], s[i][1], s[i][2], s[i][3]);
        }
        __syncthreads();

        // O += P @ V, float4 over key index j
        #pragma unroll
        for (int jq = 0; jq < 16; jq++) {
            float4 p4[4], v4[4];
            #pragma unroll
            for (int i = 0; i < 4; i++)
                p4[i] = *(const float4*)&Ps[(ty * 4 + i) * RS + jq * 4];
            #pragma unroll
            for (int j = 0; j < 4; j++)
                v4[j] = *(const float4*)&Vt[(tx * 4 + j) * RS + jq * 4];
            #pragma unroll
            for (int i = 0; i < 4; i++)
                #pragma unroll
                for (int j = 0; j < 4; j++) {
                    acc[i][j] = fmaf(p4[i].x, v4[j].x, acc[i][j]);
                    acc[i][j] = fmaf(p4[i].y, v4[j].y, acc[i][j]);
                    acc[i][j] = fmaf(p4[i].z, v4[j].z, acc[i][j]);
                    acc[i][j] = fmaf(p4[i].w, v4[j].w, acc[i][j]);
                }
        }
    }

    // Write normalized output: out[b, n, h*DH + d]
    #pragma unroll
    for (int i = 0; i < 4; i++) {
        int r = rt * 64 + ty * 4 + i;
        float inv = 1.0f / l[i];
        size_t obase = ((size_t)b * N_ + r) * INNER + h * DH + tx * 4;
        #pragma unroll
        for (int j = 0; j < 4; j++)
            out[obase + j] = acc[i][j] * inv;
    }
}

// ---------------------------------------------------------------------------
// Launch
// ---------------------------------------------------------------------------
extern "C" void kernel_launch(void* const* d_in, const int* in_sizes, int n_in,
                              void* d_out, int out_size)
{
    const float* x    = (const float*)d_in[0];   // [8,1024,768]
    const float* Wqkv = (const float*)d_in[1];   // [768,2304]
    const float* Wout = (const float*)d_in[2];   // [768,768]
    const int*   perm = (const int*)d_in[3];     // [65536]
    float* out = (float*)d_out;

    float *qkv, *att;
    cudaGetSymbolAddress((void**)&qkv, g_qkv);
    cudaGetSymbolAddress((void**)&att, g_att);
    cudaFuncSetAttribute(attn_kernel,
                         cudaFuncAttributeMaxDynamicSharedMemorySize,
                         (int)ATTN_SMEM);

    const int M = B_ * N_;  // 8192

    // 1) QKV projection
    gemm_kernel<<<dim3(QKV3 / BN, M / BM), 256>>>(x, Wqkv, qkv, M, QKV3, DIM_);
    // 2) Shuffled-Q attention (perm gather fused into Q load)
    attn_kernel<<<dim3(B_ * HEADS, N_ / 64), 256, ATTN_SMEM>>>(qkv, perm, att);
    // 3) Output projection
    gemm_kernel<<<dim3(INNER / BN, M / BM), 256>>>(att, Wout, out, M, INNER, DIM_);
}

// round 4
// speedup vs baseline: 4.0286x; 4.0286x over previous
#include <cuda_runtime.h>
#include <cuda_bf16.h>
#include <cstdint>
#include <cstddef>

// Problem constants
#define B_    8
#define N_    1024
#define DIM_  768
#define HEADS 12
#define DH    64
#define INNER 768          // HEADS*DH
#define QKV3  2304         // 3*INNER
#define SCALE 0.125f       // DH^-0.5

// Scratch (device globals: allocation-free rule)
__device__ float g_qkv[(size_t)B_ * N_ * QKV3];   // [b, n, 3*inner]
__device__ float g_att[(size_t)B_ * N_ * INNER];  // [b, n, h*DH+d]

// ---------------------------------------------------------------------------
// tf32 helpers
// ---------------------------------------------------------------------------
__device__ __forceinline__ uint32_t f2tf32(float x) {
    uint32_t u;
    asm("cvt.rna.tf32.f32 %0, %1;" : "=r"(u) : "f"(x));
    return u;
}

__device__ __forceinline__ void mma_tf32(float c[4], const uint32_t a[4],
                                         uint32_t b0, uint32_t b1) {
    asm volatile(
        "mma.sync.aligned.m16n8k8.row.col.f32.tf32.tf32.f32 "
        "{%0,%1,%2,%3}, {%4,%5,%6,%7}, {%8,%9}, {%0,%1,%2,%3};"
        : "+f"(c[0]), "+f"(c[1]), "+f"(c[2]), "+f"(c[3])
        : "r"(a[0]), "r"(a[1]), "r"(a[2]), "r"(a[3]), "r"(b0), "r"(b1));
}

// ---------------------------------------------------------------------------
// tf32 tensor-core GEMM: C[M,N] = A[M,K] * B[K,N]  (fp32 in/out)
// Block 256 thr (8 warps, 4x2), tile 128x128x32, warp tile 32x64.
// ---------------------------------------------------------------------------
#define GBM 128
#define GBN 128
#define GBK 32
#define ASTR 36    // As row stride (floats), rows = GBM
#define BSTR 136   // Bs row stride (floats), rows = GBK

__global__ __launch_bounds__(256) void gemm_tf32_kernel(
    const float* __restrict__ A, const float* __restrict__ Bm,
    float* __restrict__ C, int M, int N, int K)
{
    __shared__ float As[GBM * ASTR];   // As[m][k]
    __shared__ float Bs[GBK * BSTR];   // Bs[k][n]

    const int tid = threadIdx.x;
    const int warpid = tid >> 5;
    const int lane = tid & 31;
    const int g   = lane >> 2;   // groupID (row within m16 / col within n8)
    const int tig = lane & 3;    // thread-in-group

    const int row0 = blockIdx.y * GBM;
    const int col0 = blockIdx.x * GBN;
    const int wm = (warpid >> 1) * 32;   // warp m offset in tile
    const int wn = (warpid & 1) * 64;    // warp n offset in tile

    float acc[2][8][4];
    #pragma unroll
    for (int mi = 0; mi < 2; mi++)
        #pragma unroll
        for (int j = 0; j < 8; j++)
            #pragma unroll
            for (int r = 0; r < 4; r++) acc[mi][j][r] = 0.f;

    for (int k0 = 0; k0 < K; k0 += GBK) {
        // A tile: 128x32 floats = 1024 float4, 4/thread
        #pragma unroll
        for (int i = 0; i < 4; i++) {
            int idx = tid + i * 256;
            int r = idx >> 3, cg = idx & 7;
            float4 v = *(const float4*)&A[(size_t)(row0 + r) * K + k0 + cg * 4];
            float* dst = &As[r * ASTR + cg * 4];
            dst[0] = __uint_as_float(f2tf32(v.x));
            dst[1] = __uint_as_float(f2tf32(v.y));
            dst[2] = __uint_as_float(f2tf32(v.z));
            dst[3] = __uint_as_float(f2tf32(v.w));
        }
        // B tile: 32x128 floats = 1024 float4, 4/thread
        #pragma unroll
        for (int i = 0; i < 4; i++) {
            int idx = tid + i * 256;
            int r = idx >> 5, cg = idx & 31;
            float4 v = *(const float4*)&Bm[(size_t)(k0 + r) * N + col0 + cg * 4];
            float* dst = &Bs[r * BSTR + cg * 4];
            dst[0] = __uint_as_float(f2tf32(v.x));
            dst[1] = __uint_as_float(f2tf32(v.y));
            dst[2] = __uint_as_float(f2tf32(v.z));
            dst[3] = __uint_as_float(f2tf32(v.w));
        }
        __syncthreads();

        #pragma unroll
        for (int kc = 0; kc < 4; kc++) {
            uint32_t a[2][4];
            #pragma unroll
            for (int mi = 0; mi < 2; mi++) {
                int r = wm + mi * 16 + g;
                a[mi][0] = __float_as_uint(As[r * ASTR + kc * 8 + tig]);
                a[mi][1] = __float_as_uint(As[(r + 8) * ASTR + kc * 8 + tig]);
                a[mi][2] = __float_as_uint(As[r * ASTR + kc * 8 + tig + 4]);
                a[mi][3] = __float_as_uint(As[(r + 8) * ASTR + kc * 8 + tig + 4]);
            }
            #pragma unroll
            for (int j = 0; j < 8; j++) {
                uint32_t b0 = __float_as_uint(Bs[(kc * 8 + tig) * BSTR + wn + j * 8 + g]);
                uint32_t b1 = __float_as_uint(Bs[(kc * 8 + tig + 4) * BSTR + wn + j * 8 + g]);
                mma_tf32(acc[0][j], a[0], b0, b1);
                mma_tf32(acc[1][j], a[1], b0, b1);
            }
        }
        __syncthreads();
    }

    // Writeback
    #pragma unroll
    for (int mi = 0; mi < 2; mi++) {
        int r0 = row0 + wm + mi * 16 + g;
        #pragma unroll
        for (int j = 0; j < 8; j++) {
            int col = col0 + wn + j * 8 + 2 * tig;
            *(float2*)&C[(size_t)r0 * N + col] =
                make_float2(acc[mi][j][0], acc[mi][j][1]);
            *(float2*)&C[(size_t)(r0 + 8) * N + col] =
                make_float2(acc[mi][j][2], acc[mi][j][3]);
        }
    }
}

// ---------------------------------------------------------------------------
// Fused shuffled-Q flash attention with tf32 MMA.
// Block 128 thr (4 warps); 64 q-rows per block, warp owns 16 rows.
// Grid: (B*HEADS, N/64).
// ---------------------------------------------------------------------------
#define AST 68                               // smem row stride (floats)
#define ATTN_SMEM (4 * 64 * AST * sizeof(float))   // Qs,Ks,Vs,Ps = 69632 B

__global__ __launch_bounds__(128) void attn_kernel(
    const float* __restrict__ qkv, const int* __restrict__ perm,
    float* __restrict__ out)
{
    extern __shared__ float sm[];
    float* Qs = sm;                  // [64][AST]  Qs[q][d]   (tf32 bits)
    float* Ks = sm + 64 * AST;       // [64][AST]  Ks[key][d]
    float* Vs = sm + 2 * 64 * AST;   // [64][AST]  Vs[key][d]
    float* Ps = sm + 3 * 64 * AST;   // [64][AST]  Ps[q][key] (per-warp rows)

    const int bh = blockIdx.x;
    const int b  = bh / HEADS, h = bh % HEADS;
    const int qt = blockIdx.y;
    const int tid = threadIdx.x;
    const int warpid = tid >> 5;
    const int lane = tid & 31;
    const int g   = lane >> 2;
    const int tig = lane & 3;
    const int wq  = warpid * 16;     // warp's q-row offset within tile

    const float* base = qkv + (size_t)b * N_ * QKV3;

    // Load shuffled Q tile (perm gather), convert to tf32.
    #pragma unroll
    for (int i = 0; i < 32; i++) {
        int idx = tid + i * 128;            // 0..4095
        int r = idx >> 6, d = idx & 63;
        int p  = perm[((qt * 64 + r) << 6) + d];
        int n2 = p >> 6, d2 = p & 63;
        Qs[r * AST + d] = __uint_as_float(
            f2tf32(base[(size_t)n2 * QKV3 + h * DH + d2]));
    }

    float o[8][4];
    #pragma unroll
    for (int j = 0; j < 8; j++)
        #pragma unroll
        for (int r = 0; r < 4; r++) o[j][r] = 0.f;
    float m0 = -1e30f, m1 = -1e30f, l0 = 0.f, l1 = 0.f;

    for (int kt = 0; kt < N_ / 64; kt++) {
        __syncthreads();   // prior tile's smem reads complete (also covers Q load)
        // Load K and V tiles (64 keys x 64 d), tf32-converted.
        #pragma unroll
        for (int i = 0; i < 8; i++) {
            int idx = tid + i * 128;        // 0..1023 float4 slots
            int key = idx >> 4, d4 = idx & 15;
            const float* rowp = base + (size_t)(kt * 64 + key) * QKV3 + h * DH;
            float4 kv = *(const float4*)(rowp + INNER + d4 * 4);
            float4 vv = *(const float4*)(rowp + 2 * INNER + d4 * 4);
            float* kd = &Ks[key * AST + d4 * 4];
            float* vd = &Vs[key * AST + d4 * 4];
            kd[0] = __uint_as_float(f2tf32(kv.x));
            kd[1] = __uint_as_float(f2tf32(kv.y));
            kd[2] = __uint_as_float(f2tf32(kv.z));
            kd[3] = __uint_as_float(f2tf32(kv.w));
            vd[0] = __uint_as_float(f2tf32(vv.x));
            vd[1] = __uint_as_float(f2tf32(vv.y));
            vd[2] = __uint_as_float(f2tf32(vv.z));
            vd[3] = __uint_as_float(f2tf32(vv.w));
        }
        __syncthreads();

        // S = Q K^T : m16 (q) x n64 (keys), k = DH = 8 k8-steps
        float s[8][4];
        #pragma unroll
        for (int j = 0; j < 8; j++)
            #pragma unroll
            for (int r = 0; r < 4; r++) s[j][r] = 0.f;

        #pragma unroll
        for (int kc = 0; kc < 8; kc++) {
            uint32_t a[4];
            int r = wq + g;
            a[0] = __float_as_uint(Qs[r * AST + kc * 8 + tig]);
            a[1] = __float_as_uint(Qs[(r + 8) * AST + kc * 8 + tig]);
            a[2] = __float_as_uint(Qs[r * AST + kc * 8 + tig + 4]);
            a[3] = __float_as_uint(Qs[(r + 8) * AST + kc * 8 + tig + 4]);
            #pragma unroll
            for (int j = 0; j < 8; j++) {
                uint32_t b0 = __float_as_uint(Ks[(j * 8 + g) * AST + kc * 8 + tig]);
                uint32_t b1 = __float_as_uint(Ks[(j * 8 + g) * AST + kc * 8 + tig + 4]);
                mma_tf32(s[j], a, b0, b1);
            }
        }

        // Online softmax. Rows: g (regs 0,1) and g+8 (regs 2,3); cols 2*tig+{0,1}.
        float mx0 = -1e30f, mx1 = -1e30f;
        #pragma unroll
        for (int j = 0; j < 8; j++) {
            s[j][0] *= SCALE; s[j][1] *= SCALE; s[j][2] *= SCALE; s[j][3] *= SCALE;
            mx0 = fmaxf(mx0, fmaxf(s[j][0], s[j][1]));
            mx1 = fmaxf(mx1, fmaxf(s[j][2], s[j][3]));
        }
        mx0 = fmaxf(mx0, __shfl_xor_sync(0xffffffffu, mx0, 1));
        mx0 = fmaxf(mx0, __shfl_xor_sync(0xffffffffu, mx0, 2));
        mx1 = fmaxf(mx1, __shfl_xor_sync(0xffffffffu, mx1, 1));
        mx1 = fmaxf(mx1, __shfl_xor_sync(0xffffffffu, mx1, 2));

        float nm0 = fmaxf(m0, mx0), nm1 = fmaxf(m1, mx1);
        float al0 = __expf(m0 - nm0), al1 = __expf(m1 - nm1);
        float rs0 = 0.f, rs1 = 0.f;
        #pragma unroll
        for (int j = 0; j < 8; j++) {
            s[j][0] = __expf(s[j][0] - nm0);
            s[j][1] = __expf(s[j][1] - nm0);
            s[j][2] = __expf(s[j][2] - nm1);
            s[j][3] = __expf(s[j][3] - nm1);
            rs0 += s[j][0] + s[j][1];
            rs1 += s[j][2] + s[j][3];
        }
        rs0 += __shfl_xor_sync(0xffffffffu, rs0, 1);
        rs0 += __shfl_xor_sync(0xffffffffu, rs0, 2);
        rs1 += __shfl_xor_sync(0xffffffffu, rs1, 1);
        rs1 += __shfl_xor_sync(0xffffffffu, rs1, 2);
        l0 = l0 * al0 + rs0; l1 = l1 * al1 + rs1;
        m0 = nm0; m1 = nm1;
        #pragma unroll
        for (int j = 0; j < 8; j++) {
            o[j][0] *= al0; o[j][1] *= al0; o[j][2] *= al1; o[j][3] *= al1;
            // Write P (tf32) to per-warp smem rows.
            int pr = wq + g;
            int pc = j * 8 + 2 * tig;
            *(float2*)&Ps[pr * AST + pc] = make_float2(
                __uint_as_float(f2tf32(s[j][0])), __uint_as_float(f2tf32(s[j][1])));
            *(float2*)&Ps[(pr + 8) * AST + pc] = make_float2(
                __uint_as_float(f2tf32(s[j][2])), __uint_as_float(f2tf32(s[j][3])));
        }
        __syncwarp();

        // O += P V : m16 (q) x n64 (d), k = 64 keys = 8 k8-steps
        #pragma unroll
        for (int kc = 0; kc < 8; kc++) {
            uint32_t a[4];
            int r = wq + g;
            a[0] = __float_as_uint(Ps[r * AST + kc * 8 + tig]);
            a[1] = __float_as_uint(Ps[(r + 8) * AST + kc * 8 + tig]);
            a[2] = __float_as_uint(Ps[r * AST + kc * 8 + tig + 4]);
            a[3] = __float_as_uint(Ps[(r + 8) * AST + kc * 8 + tig + 4]);
            #pragma unroll
            for (int j = 0; j < 8; j++) {
                uint32_t b0 = __float_as_uint(Vs[(kc * 8 + tig) * AST + j * 8 + g]);
                uint32_t b1 = __float_as_uint(Vs[(kc * 8 + tig + 4) * AST + j * 8 + g]);
                mma_tf32(o[j], a, b0, b1);
            }
        }
        __syncwarp();   // protect Ps before next iteration's writes
    }

    // Normalize and write out[b, q, h*DH + d]
    float inv0 = 1.0f / l0, inv1 = 1.0f / l1;
    int q0 = qt * 64 + wq + g;
    #pragma unroll
    for (int j = 0; j < 8; j++) {
        int d = j * 8 + 2 * tig;
        size_t o0 = ((size_t)b * N_ + q0) * INNER + h * DH + d;
        size_t o1 = ((size_t)b * N_ + q0 + 8) * INNER + h * DH + d;
        *(float2*)&out[o0] = make_float2(o[j][0] * inv0, o[j][1] * inv0);
        *(float2*)&out[o1] = make_float2(o[j][2] * inv1, o[j][3] * inv1);
    }
}

// ---------------------------------------------------------------------------
// Launch
// ---------------------------------------------------------------------------
extern "C" void kernel_launch(void* const* d_in, const int* in_sizes, int n_in,
                              void* d_out, int out_size)
{
    const float* x    = (const float*)d_in[0];   // [8,1024,768]
    const float* Wqkv = (const float*)d_in[1];   // [768,2304]
    const float* Wout = (const float*)d_in[2];   // [768,768]
    const int*   perm = (const int*)d_in[3];     // [65536]
    float* out = (float*)d_out;

    float *qkv, *att;
    cudaGetSymbolAddress((void**)&qkv, g_qkv);
    cudaGetSymbolAddress((void**)&att, g_att);
    cudaFuncSetAttribute(attn_kernel,
                         cudaFuncAttributeMaxDynamicSharedMemorySize,
                         (int)ATTN_SMEM);

    const int M = B_ * N_;  // 8192

    // 1) QKV projection (tf32 MMA)
    gemm_tf32_kernel<<<dim3(QKV3 / GBN, M / GBM), 256>>>(x, Wqkv, qkv, M, QKV3, DIM_);
    // 2) Shuffled-Q attention (perm gather fused into Q load, tf32 MMA)
    attn_kernel<<<dim3(B_ * HEADS, N_ / 64), 128, ATTN_SMEM>>>(qkv, perm, att);
    // 3) Output projection (tf32 MMA)
    gemm_tf32_kernel<<<dim3(INNER / GBN, M / GBM), 256>>>(att, Wout, out, M, INNER, DIM_);
}